// round 3
// baseline (speedup 1.0000x reference)
#include <cuda_runtime.h>
#include <math.h>

#define BB 8
#define DM 512
#define LL 4096
#define N2C 32

// ---- scratch (no allocations allowed -> __device__ globals) ----
__device__ float g_h[(size_t)BB * DM * LL];   // 64 MiB  residual stream (B,D,L)
__device__ float g_y[(size_t)BB * DM * LL];   // 64 MiB  S4D+gelu output
__device__ float g_z[(size_t)BB * DM * LL];   // 64 MiB  GLU output
__device__ float g_hm[BB * DM];               // mean over L

// ================= input projection + positional embedding =================
// h[b,d,l] = sum_c Wp[d,c] x[b,c,l] + bp[d] + pos[l,d]
__global__ void proj_kernel(const float* __restrict__ x,
                            const float* __restrict__ Wp,
                            const float* __restrict__ bp,
                            const float* __restrict__ pos)
{
    __shared__ float P[32][33];
    int lx = threadIdx.x, ty = threadIdx.y;
    int l0 = blockIdx.x * 32, d0 = blockIdx.y * 32, b = blockIdx.z;
    #pragma unroll
    for (int r = 0; r < 4; r++) {
        int ll = ty + r * 8;
        P[ll][lx] = pos[(size_t)(l0 + ll) * DM + d0 + lx];   // coalesced over d
    }
    __syncthreads();
    int l = l0 + lx;
    float x0 = x[(size_t)(b * 3 + 0) * LL + l];
    float x1 = x[(size_t)(b * 3 + 1) * LL + l];
    float x2 = x[(size_t)(b * 3 + 2) * LL + l];
    #pragma unroll
    for (int r = 0; r < 4; r++) {
        int dl = ty * 4 + r;
        int d = d0 + dl;
        float v = Wp[d * 3 + 0] * x0 + Wp[d * 3 + 1] * x1 + Wp[d * 3 + 2] * x2
                + bp[d] + P[lx][dl];
        g_h[(size_t)(b * DM + d) * LL + l] = v;
    }
}

// ================= S4D scan + Dskip + exact GELU =================
// Diagonal SSM recurrence (mathematically identical to the reference FFT conv):
//   s_n = w_n * s_n + u[l];  y[l] = 2 Re( sum_n Cc_n s_n )
// Layout: 2 channels per warp (16 lanes each), 2 complex states per lane.
__global__ __launch_bounds__(128) void ssm_kernel(
    const float* __restrict__ log_dt,     // + layer*DM
    const float* __restrict__ log_A_real, // + layer*DM*N2
    const float* __restrict__ A_imag,
    const float* __restrict__ C_re,
    const float* __restrict__ C_im,
    const float* __restrict__ Dskip)
{
    int tid  = blockIdx.x * blockDim.x + threadIdx.x;
    int w    = tid >> 5;
    int lane = tid & 31;
    int g    = lane >> 4;     // which of the 2 channels in this warp
    int sub  = lane & 15;     // lane within channel group
    int b    = w >> 8;        // 256 channel-pairs per batch
    int hch  = (w & 255) * 2 + g;

    float dt  = expf(log_dt[hch]);
    float Dsk = Dskip[hch];

    float wr[2], wi[2], Ccr[2], nCci[2];
    #pragma unroll
    for (int j = 0; j < 2; j++) {
        int n   = sub + 16 * j;
        int idx = hch * N2C + n;
        float Are = -expf(log_A_real[idx]);
        float Aim = A_imag[idx];
        float dr = Are * dt, di = Aim * dt;
        float er = expf(dr);
        float wrr = er * cosf(di), wii = er * sinf(di);
        // q = (w - 1)/A
        float nr = wrr - 1.0f, ni = wii;
        float inv = 1.0f / (Are * Are + Aim * Aim);
        float qr = (nr * Are + ni * Aim) * inv;
        float qi = (ni * Are - nr * Aim) * inv;
        float cr = C_re[idx], ci = C_im[idx];
        wr[j] = wrr; wi[j] = wii;
        Ccr[j]  =  2.0f * (cr * qr - ci * qi);   // fold the 2x from K
        nCci[j] = -2.0f * (cr * qi + ci * qr);
    }

    const float* up = g_h + (size_t)(b * DM + hch) * LL;
    float*       yp = g_y + (size_t)(b * DM + hch) * LL;

    float sr0 = 0.f, si0 = 0.f, sr1 = 0.f, si1 = 0.f;
    float ucur = up[sub];
    for (int c = 0; c < LL / 16; c++) {
        float unext = 0.f;
        if (c + 1 < LL / 16) unext = up[(c + 1) * 16 + sub];   // prefetch
        float yown = 0.f;
        #pragma unroll
        for (int t = 0; t < 16; t++) {
            float ut = __shfl_sync(0xffffffffu, ucur, t, 16);  // broadcast within 16-group
            float a0 = fmaf(-wi[0], si0, ut);
            float b0 = fmaf(wr[0], si0, wi[0] * sr0);
            sr0 = fmaf(wr[0], sr0, a0); si0 = b0;
            float a1 = fmaf(-wi[1], si1, ut);
            float b1 = fmaf(wr[1], si1, wi[1] * sr1);
            sr1 = fmaf(wr[1], sr1, a1); si1 = b1;
            float cv = Ccr[0] * sr0;
            cv = fmaf(nCci[0], si0, cv);
            cv = fmaf(Ccr[1],  sr1, cv);
            cv = fmaf(nCci[1], si1, cv);
            cv += __shfl_xor_sync(0xffffffffu, cv, 8);   // reduce over 16 lanes
            cv += __shfl_xor_sync(0xffffffffu, cv, 4);
            cv += __shfl_xor_sync(0xffffffffu, cv, 2);
            cv += __shfl_xor_sync(0xffffffffu, cv, 1);
            if (sub == t) yown = cv;
        }
        float v   = fmaf(Dsk, ucur, yown);
        float gel = 0.5f * v * (1.0f + erff(v * 0.70710678118654752f));  // exact GELU
        yp[c * 16 + sub] = gel;
        ucur = unext;
    }
}

// ================= GLU projection GEMM (fp32) with fused GLU epilogue =================
// z[m,n] = (Wa[m,:].y[:,n] + ba[m]) * sigmoid(Wb[m,:].y[:,n] + bb[m])
// Tile: 64 z-rows (=64 a-rows + 64 b-rows) x 128 cols x K16; 256 thr, 8x4 dual microtile.
#define GBM 64
#define GBN 128
#define GBK 16
#define WLD 68   // padded smem row for W tiles

__global__ __launch_bounds__(256, 2) void gemm_glu_kernel(
    const float* __restrict__ W,     // (1024, 512) row-major, + layer offset
    const float* __restrict__ bias)  // (1024,)
{
    __shared__ __align__(16) float Wa_s[GBK][WLD];
    __shared__ __align__(16) float Wb_s[GBK][WLD];
    __shared__ __align__(16) float Y_s[GBK][GBN];

    int tid = threadIdx.x;
    int n0  = blockIdx.x * GBN;
    int m0  = blockIdx.y * GBM;
    int b   = blockIdx.z;

    const float* Y = g_y + (size_t)b * DM * LL;
    float*       Z = g_z + (size_t)b * DM * LL;

    int tn = tid & 31, tm = tid >> 5;

    // load indices
    int lm  = tid >> 2;       // 0..63 W rows
    int lk4 = tid & 3;        // float4 slot along k
    int yk0 = tid >> 5;       // 0..7
    int yk1 = yk0 + 8;        // 8..15
    int ynq = tid & 31;

    const float* wa_base = W + (size_t)(m0 + lm) * DM;
    const float* wb_base = W + (size_t)(512 + m0 + lm) * DM;

    float accA[8][4], accB[8][4];
    #pragma unroll
    for (int i = 0; i < 8; i++)
        #pragma unroll
        for (int j = 0; j < 4; j++) { accA[i][j] = 0.f; accB[i][j] = 0.f; }

    float4 pWa, pWb, pY0, pY1;
    // preload k-tile 0
    pWa = *(const float4*)(wa_base + lk4 * 4);
    pWb = *(const float4*)(wb_base + lk4 * 4);
    pY0 = *(const float4*)(Y + (size_t)yk0 * LL + n0 + ynq * 4);
    pY1 = *(const float4*)(Y + (size_t)yk1 * LL + n0 + ynq * 4);

    for (int kt = 0; kt < DM / GBK; kt++) {
        __syncthreads();
        Wa_s[lk4 * 4 + 0][lm] = pWa.x;
        Wa_s[lk4 * 4 + 1][lm] = pWa.y;
        Wa_s[lk4 * 4 + 2][lm] = pWa.z;
        Wa_s[lk4 * 4 + 3][lm] = pWa.w;
        Wb_s[lk4 * 4 + 0][lm] = pWb.x;
        Wb_s[lk4 * 4 + 1][lm] = pWb.y;
        Wb_s[lk4 * 4 + 2][lm] = pWb.z;
        Wb_s[lk4 * 4 + 3][lm] = pWb.w;
        *(float4*)&Y_s[yk0][ynq * 4] = pY0;
        *(float4*)&Y_s[yk1][ynq * 4] = pY1;
        __syncthreads();

        int kn = (kt + 1) * GBK;
        if (kn < DM) {   // register prefetch of the next k-tile
            pWa = *(const float4*)(wa_base + kn + lk4 * 4);
            pWb = *(const float4*)(wb_base + kn + lk4 * 4);
            pY0 = *(const float4*)(Y + (size_t)(kn + yk0) * LL + n0 + ynq * 4);
            pY1 = *(const float4*)(Y + (size_t)(kn + yk1) * LL + n0 + ynq * 4);
        }

        #pragma unroll
        for (int k = 0; k < GBK; k++) {
            float4 a0 = *(const float4*)&Wa_s[k][tm * 8];
            float4 a1 = *(const float4*)&Wa_s[k][tm * 8 + 4];
            float4 c0 = *(const float4*)&Wb_s[k][tm * 8];
            float4 c1 = *(const float4*)&Wb_s[k][tm * 8 + 4];
            float4 yv = *(const float4*)&Y_s[k][tn * 4];
            float wa[8] = {a0.x, a0.y, a0.z, a0.w, a1.x, a1.y, a1.z, a1.w};
            float wb[8] = {c0.x, c0.y, c0.z, c0.w, c1.x, c1.y, c1.z, c1.w};
            float yy[4] = {yv.x, yv.y, yv.z, yv.w};
            #pragma unroll
            for (int i = 0; i < 8; i++)
                #pragma unroll
                for (int j = 0; j < 4; j++) {
                    accA[i][j] = fmaf(wa[i], yy[j], accA[i][j]);
                    accB[i][j] = fmaf(wb[i], yy[j], accB[i][j]);
                }
        }
    }

    // fused GLU epilogue
    #pragma unroll
    for (int i = 0; i < 8; i++) {
        int m = m0 + tm * 8 + i;
        float ba = bias[m];
        float bb = bias[m + 512];
        float4 zs;
        float a0 = accA[i][0] + ba, b0 = accB[i][0] + bb;
        float a1 = accA[i][1] + ba, b1 = accB[i][1] + bb;
        float a2 = accA[i][2] + ba, b2 = accB[i][2] + bb;
        float a3 = accA[i][3] + ba, b3 = accB[i][3] + bb;
        zs.x = a0 / (1.0f + expf(-b0));
        zs.y = a1 / (1.0f + expf(-b1));
        zs.z = a2 / (1.0f + expf(-b2));
        zs.w = a3 / (1.0f + expf(-b3));
        *(float4*)&Z[(size_t)m * LL + n0 + tn * 4] = zs;
    }
}

// ================= residual + LayerNorm over D (in place into g_h) =================
__global__ void ln_kernel(const float* __restrict__ gam, const float* __restrict__ bet)
{
    int lx = threadIdx.x, ty = threadIdx.y;
    int l = blockIdx.x * 32 + lx;
    int b = blockIdx.y;
    __shared__ float R1[8][32], R2[8][32];
    size_t base = (size_t)b * DM * LL + l;
    float s = 0.f, q = 0.f;
    for (int d = ty; d < DM; d += 8) {
        size_t idx = base + (size_t)d * LL;
        float v = g_h[idx] + g_z[idx];
        s += v; q = fmaf(v, v, q);
    }
    R1[ty][lx] = s; R2[ty][lx] = q;
    __syncthreads();
    if (ty == 0) {
        float S = 0.f, Q = 0.f;
        #pragma unroll
        for (int r = 0; r < 8; r++) { S += R1[r][lx]; Q += R2[r][lx]; }
        float mu = S * (1.0f / DM);
        float var = Q * (1.0f / DM) - mu * mu;
        R1[0][lx] = mu;
        R2[0][lx] = rsqrtf(var + 1e-5f);
    }
    __syncthreads();
    float mu = R1[0][lx], rs = R2[0][lx];
    for (int d = ty; d < DM; d += 8) {
        size_t idx = base + (size_t)d * LL;
        float v = g_h[idx] + g_z[idx];
        g_h[idx] = (v - mu) * rs * gam[d] + bet[d];
    }
}

// ================= mean over L =================
__global__ void mean_kernel()
{
    int row = blockIdx.x;                 // b*DM + d
    size_t base = (size_t)row * LL;
    float s = 0.f;
    for (int l = threadIdx.x; l < LL; l += 128) s += g_h[base + l];
    #pragma unroll
    for (int o = 16; o; o >>= 1) s += __shfl_xor_sync(0xffffffffu, s, o);
    __shared__ float sm[4];
    int wid = threadIdx.x >> 5;
    if ((threadIdx.x & 31) == 0) sm[wid] = s;
    __syncthreads();
    if (threadIdx.x == 0)
        g_hm[row] = (sm[0] + sm[1] + sm[2] + sm[3]) * (1.0f / LL);
}

// ================= stats head: stats = hm @ Wstats^T + bstats; split mu/log_sig =================
__global__ void stats_kernel(const float* __restrict__ Ws,
                             const float* __restrict__ bs,
                             float* __restrict__ out)
{
    int w = (blockIdx.x * blockDim.x + threadIdx.x) >> 5;  // 4096 warps
    int lane = threadIdx.x & 31;
    int b = w >> 9;
    int o = w & 511;
    const float* hm = g_hm + b * DM;
    const float* wrow = Ws + (size_t)o * DM;
    float s = 0.f;
    for (int d = lane; d < DM; d += 32) s = fmaf(wrow[d], hm[d], s);
    #pragma unroll
    for (int off = 16; off; off >>= 1) s += __shfl_xor_sync(0xffffffffu, s, off);
    if (lane == 0) {
        float v = s + bs[o];
        if (o < 256) out[b * 256 + o] = v;                   // mu
        else         out[2048 + b * 256 + (o - 256)] = v;    // log_sig
    }
}

// ================= launch =================
extern "C" void kernel_launch(void* const* d_in, const int* in_sizes, int n_in,
                              void* d_out, int out_size)
{
    const float* x      = (const float*)d_in[0];
    const float* Wproj  = (const float*)d_in[1];
    const float* bproj  = (const float*)d_in[2];
    const float* pos    = (const float*)d_in[3];
    const float* log_dt = (const float*)d_in[4];
    const float* logAre = (const float*)d_in[5];
    const float* Aim    = (const float*)d_in[6];
    const float* Cre    = (const float*)d_in[7];
    const float* Cim    = (const float*)d_in[8];
    const float* Dsk    = (const float*)d_in[9];
    const float* Wout   = (const float*)d_in[10];
    const float* bout   = (const float*)d_in[11];
    const float* lng    = (const float*)d_in[12];
    const float* lnb    = (const float*)d_in[13];
    const float* Wstats = (const float*)d_in[14];
    const float* bstats = (const float*)d_in[15];
    float* out = (float*)d_out;

    proj_kernel<<<dim3(LL / 32, DM / 32, BB), dim3(32, 8)>>>(x, Wproj, bproj, pos);

    for (int layer = 0; layer < 4; ++layer) {
        ssm_kernel<<<512, 128>>>(log_dt + layer * DM,
                                 logAre + (size_t)layer * DM * N2C,
                                 Aim    + (size_t)layer * DM * N2C,
                                 Cre    + (size_t)layer * DM * N2C,
                                 Cim    + (size_t)layer * DM * N2C,
                                 Dsk    + layer * DM);
        gemm_glu_kernel<<<dim3(LL / GBN, DM / GBM, BB), 256>>>(
            Wout + (size_t)layer * 2 * DM * DM, bout + layer * 2 * DM);
        ln_kernel<<<dim3(LL / 32, BB), dim3(32, 8)>>>(lng + layer * DM, lnb + layer * DM);
    }

    mean_kernel<<<BB * DM, 128>>>();
    stats_kernel<<<512, 256>>>(Wstats, bstats, out);
}

// round 5
// speedup vs baseline: 1.0593x; 1.0593x over previous
#include <cuda_runtime.h>
#include <math.h>

#define BB 8
#define DM 512
#define LL 4096
#define N2C 32

typedef unsigned long long u64;

union F2 { u64 u; float2 f; };

__device__ __forceinline__ u64 fma2(u64 a, u64 b, u64 c) {
    u64 d; asm("fma.rn.f32x2 %0, %1, %2, %3;" : "=l"(d) : "l"(a), "l"(b), "l"(c)); return d;
}
__device__ __forceinline__ u64 mul2(u64 a, u64 b) {
    u64 d; asm("mul.rn.f32x2 %0, %1, %2;" : "=l"(d) : "l"(a), "l"(b)); return d;
}
__device__ __forceinline__ u64 pack2(float lo, float hi) {
    u64 d; asm("mov.b64 %0, {%1, %2};" : "=l"(d) : "f"(lo), "f"(hi)); return d;
}

// ---- scratch (no allocations allowed -> __device__ globals) ----
__device__ float g_h[(size_t)BB * DM * LL];   // 64 MiB  residual stream (B,D,L)
__device__ float g_y[(size_t)BB * DM * LL];   // 64 MiB  S4D+gelu output
__device__ float g_z[(size_t)BB * DM * LL];   // 64 MiB  GLU output
__device__ float g_hm[BB * DM];               // mean over L

// ================= input projection + positional embedding =================
__global__ void proj_kernel(const float* __restrict__ x,
                            const float* __restrict__ Wp,
                            const float* __restrict__ bp,
                            const float* __restrict__ pos)
{
    __shared__ float P[32][33];
    int lx = threadIdx.x, ty = threadIdx.y;
    int l0 = blockIdx.x * 32, d0 = blockIdx.y * 32, b = blockIdx.z;
    #pragma unroll
    for (int r = 0; r < 4; r++) {
        int ll = ty + r * 8;
        P[ll][lx] = pos[(size_t)(l0 + ll) * DM + d0 + lx];
    }
    __syncthreads();
    int l = l0 + lx;
    float x0 = x[(size_t)(b * 3 + 0) * LL + l];
    float x1 = x[(size_t)(b * 3 + 1) * LL + l];
    float x2 = x[(size_t)(b * 3 + 2) * LL + l];
    #pragma unroll
    for (int r = 0; r < 4; r++) {
        int dl = ty * 4 + r;
        int d = d0 + dl;
        float v = Wp[d * 3 + 0] * x0 + Wp[d * 3 + 1] * x1 + Wp[d * 3 + 2] * x2
                + bp[d] + P[lx][dl];
        g_h[(size_t)(b * DM + d) * LL + l] = v;
    }
}

// ================= S4D scan + Dskip + exact GELU =================
// Diagonal SSM recurrence: s_n = w_n*s_n + u[l]; y[l] = 2Re(sum_n Cc_n s_n).
// 2 channels per warp (16 lanes each); 2 complex states per lane packed f32x2.
// u is loaded directly by every lane (L1 broadcast) so the serial chain is
// just 2 dependent packed FMAs per step; the butterfly reduce is off-path.
__global__ __launch_bounds__(128) void ssm_kernel(
    const float* __restrict__ log_dt,
    const float* __restrict__ log_A_real,
    const float* __restrict__ A_imag,
    const float* __restrict__ C_re,
    const float* __restrict__ C_im,
    const float* __restrict__ Dskip)
{
    int tid  = blockIdx.x * blockDim.x + threadIdx.x;
    int w    = tid >> 5;
    int lane = tid & 31;
    int g    = lane >> 4;
    int sub  = lane & 15;
    int b    = w >> 8;
    int hch  = (w & 255) * 2 + g;

    float dt  = expf(log_dt[hch]);
    float Dsk = Dskip[hch];

    float wrv[2], wiv[2], Ccrv[2], nCciv[2];
    #pragma unroll
    for (int j = 0; j < 2; j++) {
        int n   = sub + 16 * j;
        int idx = hch * N2C + n;
        float Are = -expf(log_A_real[idx]);
        float Aim = A_imag[idx];
        float dr = Are * dt, di = Aim * dt;
        float er = expf(dr);
        float wrr = er * cosf(di), wii = er * sinf(di);
        float nr = wrr - 1.0f, ni = wii;
        float inv = 1.0f / (Are * Are + Aim * Aim);
        float qr = (nr * Are + ni * Aim) * inv;
        float qi = (ni * Are - nr * Aim) * inv;
        float cr = C_re[idx], ci = C_im[idx];
        wrv[j] = wrr; wiv[j] = wii;
        Ccrv[j]  =  2.0f * (cr * qr - ci * qi);
        nCciv[j] = -2.0f * (cr * qi + ci * qr);
    }
    u64 wr2   = pack2(wrv[0],  wrv[1]);
    u64 wi2   = pack2(wiv[0],  wiv[1]);
    u64 nwi2  = pack2(-wiv[0], -wiv[1]);
    u64 Ccr2  = pack2(Ccrv[0], Ccrv[1]);
    u64 nCci2 = pack2(nCciv[0], nCciv[1]);

    const float* up = g_h + (size_t)(b * DM + hch) * LL;
    float*       yp = g_y + (size_t)(b * DM + hch) * LL;

    u64 sr2 = 0ull, si2 = 0ull;      // (0.f, 0.f)

    float4 uv[4], nv[4];
    #pragma unroll
    for (int q = 0; q < 4; q++) uv[q] = *(const float4*)(up + q * 4);

    for (int c = 0; c < LL / 16; c++) {
        if (c + 1 < LL / 16) {
            #pragma unroll
            for (int q = 0; q < 4; q++)
                nv[q] = *(const float4*)(up + (c + 1) * 16 + q * 4);
        }
        float yown = 0.f, uown = 0.f;
        #pragma unroll
        for (int t = 0; t < 16; t++) {
            float ut;
            {
                float4 vq = uv[t >> 2];
                int cc = t & 3;
                ut = (cc == 0) ? vq.x : (cc == 1) ? vq.y : (cc == 2) ? vq.z : vq.w;
            }
            u64 ut2 = pack2(ut, ut);
            u64 a2  = fma2(nwi2, si2, ut2);                 // -wi*si + u
            u64 b2  = fma2(wr2, si2, mul2(wi2, sr2));       // wr*si + wi*sr  (old sr)
            sr2 = fma2(wr2, sr2, a2);                       // wr*sr - wi*si + u
            si2 = b2;
            F2 cvp; cvp.u = fma2(nCci2, si2, mul2(Ccr2, sr2));
            float cv = cvp.f.x + cvp.f.y;
            cv += __shfl_xor_sync(0xffffffffu, cv, 8);
            cv += __shfl_xor_sync(0xffffffffu, cv, 4);
            cv += __shfl_xor_sync(0xffffffffu, cv, 2);
            cv += __shfl_xor_sync(0xffffffffu, cv, 1);
            if (sub == t) { yown = cv; uown = ut; }
        }
        float v   = fmaf(Dsk, uown, yown);
        float gel = 0.5f * v * (1.0f + erff(v * 0.70710678118654752f));
        yp[c * 16 + sub] = gel;
        #pragma unroll
        for (int q = 0; q < 4; q++) uv[q] = nv[q];
    }
}

// ================= GLU projection GEMM: packed f32x2 (FFMA2) =================
// z[m,n] = (Wa[m,:].y[:,n] + ba[m]) * sigmoid(Wb[m,:].y[:,n] + bb[m])
// 64(a)+64(b) rows x 128 cols x K16 per block; 8x4 microtile vectorized over
// row PAIRS so the packed operands load directly as ulonglong2 from smem.
#define GBM 64
#define GBN 128
#define GBK 16
#define WLD 68

__global__ __launch_bounds__(256, 2) void gemm_glu_kernel(
    const float* __restrict__ W,     // (1024, 512) row-major, + layer offset
    const float* __restrict__ bias)  // (1024,)
{
    __shared__ __align__(16) float Wa_s[GBK][WLD];
    __shared__ __align__(16) float Wb_s[GBK][WLD];
    __shared__ __align__(16) float Y_s[GBK][GBN];

    int tid = threadIdx.x;
    int n0  = blockIdx.x * GBN;
    int m0  = blockIdx.y * GBM;
    int b   = blockIdx.z;

    const float* Y = g_y + (size_t)b * DM * LL;
    float*       Z = g_z + (size_t)b * DM * LL;

    int tn = tid & 31, tm = tid >> 5;

    int lm  = tid >> 2;
    int lk4 = tid & 3;
    int yk0 = tid >> 5;
    int yk1 = yk0 + 8;
    int ynq = tid & 31;

    const float* wa_base = W + (size_t)(m0 + lm) * DM;
    const float* wb_base = W + (size_t)(512 + m0 + lm) * DM;

    u64 accA2[4][4], accB2[4][4];
    #pragma unroll
    for (int i = 0; i < 4; i++)
        #pragma unroll
        for (int j = 0; j < 4; j++) { accA2[i][j] = 0ull; accB2[i][j] = 0ull; }

    float4 pWa, pWb, pY0, pY1;
    pWa = *(const float4*)(wa_base + lk4 * 4);
    pWb = *(const float4*)(wb_base + lk4 * 4);
    pY0 = *(const float4*)(Y + (size_t)yk0 * LL + n0 + ynq * 4);
    pY1 = *(const float4*)(Y + (size_t)yk1 * LL + n0 + ynq * 4);

    for (int kt = 0; kt < DM / GBK; kt++) {
        __syncthreads();
        Wa_s[lk4 * 4 + 0][lm] = pWa.x;
        Wa_s[lk4 * 4 + 1][lm] = pWa.y;
        Wa_s[lk4 * 4 + 2][lm] = pWa.z;
        Wa_s[lk4 * 4 + 3][lm] = pWa.w;
        Wb_s[lk4 * 4 + 0][lm] = pWb.x;
        Wb_s[lk4 * 4 + 1][lm] = pWb.y;
        Wb_s[lk4 * 4 + 2][lm] = pWb.z;
        Wb_s[lk4 * 4 + 3][lm] = pWb.w;
        *(float4*)&Y_s[yk0][ynq * 4] = pY0;
        *(float4*)&Y_s[yk1][ynq * 4] = pY1;
        __syncthreads();

        int kn = (kt + 1) * GBK;
        if (kn < DM) {
            pWa = *(const float4*)(wa_base + kn + lk4 * 4);
            pWb = *(const float4*)(wb_base + kn + lk4 * 4);
            pY0 = *(const float4*)(Y + (size_t)(kn + yk0) * LL + n0 + ynq * 4);
            pY1 = *(const float4*)(Y + (size_t)(kn + yk1) * LL + n0 + ynq * 4);
        }

        #pragma unroll
        for (int k = 0; k < GBK; k++) {
            // W tile reads are warp-uniform (tm constant per warp) -> smem broadcast
            ulonglong2 qa0 = *(const ulonglong2*)&Wa_s[k][tm * 8];
            ulonglong2 qa1 = *(const ulonglong2*)&Wa_s[k][tm * 8 + 4];
            ulonglong2 qb0 = *(const ulonglong2*)&Wb_s[k][tm * 8];
            ulonglong2 qb1 = *(const ulonglong2*)&Wb_s[k][tm * 8 + 4];
            float4 yv = *(const float4*)&Y_s[k][tn * 4];
            u64 wa2v[4] = {qa0.x, qa0.y, qa1.x, qa1.y};
            u64 wb2v[4] = {qb0.x, qb0.y, qb1.x, qb1.y};
            u64 y2[4] = {pack2(yv.x, yv.x), pack2(yv.y, yv.y),
                         pack2(yv.z, yv.z), pack2(yv.w, yv.w)};
            #pragma unroll
            for (int i = 0; i < 4; i++)
                #pragma unroll
                for (int j = 0; j < 4; j++) {
                    accA2[i][j] = fma2(wa2v[i], y2[j], accA2[i][j]);
                    accB2[i][j] = fma2(wb2v[i], y2[j], accB2[i][j]);
                }
        }
    }

    // fused GLU epilogue
    #pragma unroll
    for (int p = 0; p < 4; p++) {
        #pragma unroll
        for (int h = 0; h < 2; h++) {
            int m = m0 + tm * 8 + 2 * p + h;
            float ba = bias[m];
            float bb = bias[m + 512];
            float av[4], bv[4];
            #pragma unroll
            for (int j = 0; j < 4; j++) {
                F2 fa; fa.u = accA2[p][j];
                F2 fb; fb.u = accB2[p][j];
                av[j] = (h ? fa.f.y : fa.f.x) + ba;
                bv[j] = (h ? fb.f.y : fb.f.x) + bb;
            }
            float4 zs;
            zs.x = av[0] / (1.0f + expf(-bv[0]));
            zs.y = av[1] / (1.0f + expf(-bv[1]));
            zs.z = av[2] / (1.0f + expf(-bv[2]));
            zs.w = av[3] / (1.0f + expf(-bv[3]));
            *(float4*)&Z[(size_t)m * LL + n0 + tn * 4] = zs;
        }
    }
}

// ================= residual + LayerNorm over D (single pass, value cache) ====
__global__ __launch_bounds__(256) void ln_kernel(const float* __restrict__ gam,
                                                 const float* __restrict__ bet)
{
    int lx = threadIdx.x, ty = threadIdx.y;
    int l = blockIdx.x * 32 + lx;
    int b = blockIdx.y;
    __shared__ float R1[8][32], R2[8][32];
    size_t base = (size_t)b * DM * LL + l;
    float v[64];
    float s = 0.f, q = 0.f;
    #pragma unroll
    for (int r = 0; r < 64; r++) {
        int d = ty + r * 8;
        size_t idx = base + (size_t)d * LL;
        float vv = g_h[idx] + g_z[idx];
        v[r] = vv;
        s += vv; q = fmaf(vv, vv, q);
    }
    R1[ty][lx] = s; R2[ty][lx] = q;
    __syncthreads();
    if (ty == 0) {
        float S = 0.f, Q = 0.f;
        #pragma unroll
        for (int r = 0; r < 8; r++) { S += R1[r][lx]; Q += R2[r][lx]; }
        float mu = S * (1.0f / DM);
        float var = Q * (1.0f / DM) - mu * mu;
        R1[0][lx] = mu;
        R2[0][lx] = rsqrtf(var + 1e-5f);
    }
    __syncthreads();
    float mu = R1[0][lx], rs = R2[0][lx];
    #pragma unroll
    for (int r = 0; r < 64; r++) {
        int d = ty + r * 8;
        size_t idx = base + (size_t)d * LL;
        g_h[idx] = (v[r] - mu) * rs * gam[d] + bet[d];
    }
}

// ================= mean over L =================
__global__ void mean_kernel()
{
    int row = blockIdx.x;
    size_t base = (size_t)row * LL;
    float s = 0.f;
    for (int l = threadIdx.x; l < LL; l += 128) s += g_h[base + l];
    #pragma unroll
    for (int o = 16; o; o >>= 1) s += __shfl_xor_sync(0xffffffffu, s, o);
    __shared__ float sm[4];
    int wid = threadIdx.x >> 5;
    if ((threadIdx.x & 31) == 0) sm[wid] = s;
    __syncthreads();
    if (threadIdx.x == 0)
        g_hm[row] = (sm[0] + sm[1] + sm[2] + sm[3]) * (1.0f / LL);
}

// ================= stats head =================
__global__ void stats_kernel(const float* __restrict__ Ws,
                             const float* __restrict__ bs,
                             float* __restrict__ out)
{
    int w = (blockIdx.x * blockDim.x + threadIdx.x) >> 5;
    int lane = threadIdx.x & 31;
    int b = w >> 9;
    int o = w & 511;
    const float* hm = g_hm + b * DM;
    const float* wrow = Ws + (size_t)o * DM;
    float s = 0.f;
    for (int d = lane; d < DM; d += 32) s = fmaf(wrow[d], hm[d], s);
    #pragma unroll
    for (int off = 16; off; off >>= 1) s += __shfl_xor_sync(0xffffffffu, s, off);
    if (lane == 0) {
        float v = s + bs[o];
        if (o < 256) out[b * 256 + o] = v;
        else         out[2048 + b * 256 + (o - 256)] = v;
    }
}

// ================= launch =================
extern "C" void kernel_launch(void* const* d_in, const int* in_sizes, int n_in,
                              void* d_out, int out_size)
{
    const float* x      = (const float*)d_in[0];
    const float* Wproj  = (const float*)d_in[1];
    const float* bproj  = (const float*)d_in[2];
    const float* pos    = (const float*)d_in[3];
    const float* log_dt = (const float*)d_in[4];
    const float* logAre = (const float*)d_in[5];
    const float* Aim    = (const float*)d_in[6];
    const float* Cre    = (const float*)d_in[7];
    const float* Cim    = (const float*)d_in[8];
    const float* Dsk    = (const float*)d_in[9];
    const float* Wout   = (const float*)d_in[10];
    const float* bout   = (const float*)d_in[11];
    const float* lng    = (const float*)d_in[12];
    const float* lnb    = (const float*)d_in[13];
    const float* Wstats = (const float*)d_in[14];
    const float* bstats = (const float*)d_in[15];
    float* out = (float*)d_out;

    proj_kernel<<<dim3(LL / 32, DM / 32, BB), dim3(32, 8)>>>(x, Wproj, bproj, pos);

    for (int layer = 0; layer < 4; ++layer) {
        ssm_kernel<<<512, 128>>>(log_dt + layer * DM,
                                 logAre + (size_t)layer * DM * N2C,
                                 Aim    + (size_t)layer * DM * N2C,
                                 Cre    + (size_t)layer * DM * N2C,
                                 Cim    + (size_t)layer * DM * N2C,
                                 Dsk    + layer * DM);
        gemm_glu_kernel<<<dim3(LL / GBN, DM / GBM, BB), 256>>>(
            Wout + (size_t)layer * 2 * DM * DM, bout + layer * 2 * DM);
        ln_kernel<<<dim3(LL / 32, BB), dim3(32, 8)>>>(lng + layer * DM, lnb + layer * DM);
    }

    mean_kernel<<<BB * DM, 128>>>();
    stats_kernel<<<512, 256>>>(Wstats, bstats, out);
}